// round 16
// baseline (speedup 1.0000x reference)
#include <cuda_runtime.h>
#include <cuda_bf16.h>
#include <math.h>
#include <cstdint>

#define N_SAMP 1024
#define N_FEAT 512
#define N_LAB  16

#define THRESH   0.5f
#define MARGIN   0.1f
#define SCALE_P  0.05f
#define SCALE_N  0.002f
#define ONE_EPS  0.99999f   // 1.0 - 1e-5

#define NCTA 148
#define NTHR 1024

// ---- scratch (no allocations allowed) ----
__device__ float          g_sim[N_SAMP * N_SAMP];        // 4 MB, L2-resident
__device__ __nv_bfloat16  g_hi[N_SAMP * N_FEAT];         // 1 MB
__device__ __nv_bfloat16  g_lo[N_SAMP * N_FEAT];         // 1 MB
__device__ unsigned       g_posmask[N_LAB][N_SAMP / 32];
__device__ float          g_partial[NCTA];
__device__ unsigned       bar_cnt[4];                    // zero-init, self-resetting
__device__ unsigned       bar_gen[4];                    // monotone across replays

// ============================================================
// PTX helpers (baseline ISA only)
// ============================================================
__device__ __forceinline__ uint32_t smem_u32(const void* p) {
    uint32_t a;
    asm("{ .reg .u64 t; cvta.to.shared.u64 t, %1; cvt.u32.u64 %0, t; }" : "=r"(a) : "l"(p));
    return a;
}
#define CP_ASYNC16(s, g) asm volatile("cp.async.cg.shared.global [%0], [%1], 16;" :: "r"(s), "l"(g) : "memory")
#define CP_COMMIT()      asm volatile("cp.async.commit_group;" ::: "memory")
#define CP_WAIT1()       asm volatile("cp.async.wait_group 1;" ::: "memory")
#define CP_WAIT0()       asm volatile("cp.async.wait_group 0;" ::: "memory")

__device__ __forceinline__ void ldmatrix4(uint32_t* r, uint32_t addr) {
    asm volatile("ldmatrix.sync.aligned.m8n8.x4.shared.b16 {%0,%1,%2,%3}, [%4];"
        : "=r"(r[0]), "=r"(r[1]), "=r"(r[2]), "=r"(r[3]) : "r"(addr));
}
__device__ __forceinline__ void ldmatrix2(uint32_t* r, uint32_t addr) {
    asm volatile("ldmatrix.sync.aligned.m8n8.x2.shared.b16 {%0,%1}, [%2];"
        : "=r"(r[0]), "=r"(r[1]) : "r"(addr));
}
__device__ __forceinline__ void mma16816(float* d, const uint32_t* a, const uint32_t* b) {
    asm volatile("mma.sync.aligned.m16n8k16.row.col.f32.bf16.bf16.f32 "
        "{%0,%1,%2,%3}, {%4,%5,%6,%7}, {%8,%9}, {%0,%1,%2,%3};"
        : "+f"(d[0]), "+f"(d[1]), "+f"(d[2]), "+f"(d[3])
        : "r"(a[0]), "r"(a[1]), "r"(a[2]), "r"(a[3]), "r"(b[0]), "r"(b[1]));
}
#define SW128(off) ((off) ^ (((off) >> 3) & 0x70))

// Taylor exp: strictly monotone, pure FMA.
__device__ __forceinline__ float exp_poly4(float x) {   // |x| <= 0.08
    float e = fmaf(x, 1.f / 24.f, 1.f / 6.f);
    e = fmaf(x, e, 0.5f);
    e = fmaf(x, e, 1.0f);
    e = fmaf(x, e, 1.0f);
    return e;
}
__device__ __forceinline__ float exp_poly3(float x) {   // |x| <= 0.004
    float e = fmaf(x, 1.f / 6.f, 0.5f);
    e = fmaf(x, e, 1.0f);
    e = fmaf(x, e, 1.0f);
    return e;
}

// Device-wide barrier: all NCTA CTAs resident (grid 148 <= SM count, occ >= 1).
__device__ __forceinline__ void grid_sync(int b) {
    __syncthreads();
    if (threadIdx.x == 0) {
        __threadfence();
        unsigned g;
        asm volatile("ld.acquire.gpu.u32 %0, [%1];" : "=r"(g) : "l"(&bar_gen[b]));
        unsigned t = atomicAdd(&bar_cnt[b], 1u);
        if (t == NCTA - 1) {
            bar_cnt[b] = 0;
            asm volatile("st.release.gpu.u32 [%0], %1;" :: "l"(&bar_gen[b]), "r"(g + 1u));
        } else {
            unsigned cur;
            do {
                asm volatile("ld.acquire.gpu.u32 %0, [%1];" : "=r"(cur) : "l"(&bar_gen[b]));
            } while (cur == g);
        }
    }
    __syncthreads();
}

// ============================================================
// MMA tile helpers (triangular 64x64, 3-stage ring)
// ============================================================
#define STAGE_BYTES 32768            // 8KB x (Ahi, Alo, Bhi, Blo)
#define SM_TOTAL (3 * STAGE_BYTES)

__device__ __forceinline__ void issue_chunk64(uint32_t sBase, int tid, int bm, int bn, int kc) {
#pragma unroll
    for (int k2 = 0; k2 < 2; k2++) {
        int u = tid + k2 * 1024;            // 0..2047
        int st = u >> 9;                    // buffer 0..3
        int within = u & 511;
        int r = within >> 3, seg = within & 7;
        const __nv_bfloat16* src = (st == 0 || st == 2) ? g_hi : g_lo;
        const int rowbase = (st < 2) ? bm : bn;
        const char* g = (const char*)(src + (size_t)(rowbase + r) * N_FEAT + kc) + seg * 16;
        CP_ASYNC16(sBase + st * 8192 + SW128((uint32_t)(r * 128 + seg * 16)), g);
    }
    CP_COMMIT();
}

// ============================================================
// THE fused persistent kernel.  <<<148, 1024, 96KB>>>
// ============================================================
__global__ void __launch_bounds__(1024, 1) fused_kernel(const float* __restrict__ F,
                                                        const int* __restrict__ labels,
                                                        float* __restrict__ out) {
    extern __shared__ char smem[];
    const uint32_t sb = smem_u32(smem);
    const int cta  = blockIdx.x;
    const int tid  = threadIdx.x;
    const int wid  = tid >> 5;
    const int lane = tid & 31;

    __shared__ float warpres[32];
    __shared__ float redf[32];
    __shared__ int   redi[32];
    __shared__ int   s_last;

    // ================= phase 0: labels (CTA 0) + conv (CTAs 1..147) ========
    if (cta == 0) {
        const int row = wid * 32 + lane;
        const int4* lp = (const int4*)(labels + row * N_LAB);
        int4 L0 = lp[0], L1 = lp[1], L2 = lp[2], L3 = lp[3];
        int lab[16] = { L0.x, L0.y, L0.z, L0.w, L1.x, L1.y, L1.z, L1.w,
                        L2.x, L2.y, L2.z, L2.w, L3.x, L3.y, L3.z, L3.w };
#pragma unroll
        for (int c = 0; c < 16; c++) {
            unsigned m = __ballot_sync(0xffffffffu, lab[c] == 1);
            if (lane == c) g_posmask[c][wid] = m;
        }
    } else {
        const int idx = (cta - 1) * NTHR + tid;
        for (int gid = idx; gid < (N_SAMP * N_FEAT / 4); gid += 147 * NTHR) {
            float4 v = ((const float4*)F)[gid];
            __nv_bfloat16 hx = __float2bfloat16(v.x);
            __nv_bfloat16 hy = __float2bfloat16(v.y);
            __nv_bfloat16 hz = __float2bfloat16(v.z);
            __nv_bfloat16 hw = __float2bfloat16(v.w);
            __nv_bfloat16 lx = __float2bfloat16(v.x - __bfloat162float(hx));
            __nv_bfloat16 ly = __float2bfloat16(v.y - __bfloat162float(hy));
            __nv_bfloat16 lz = __float2bfloat16(v.z - __bfloat162float(hz));
            __nv_bfloat16 lw = __float2bfloat16(v.w - __bfloat162float(hw));
            __nv_bfloat162* ho = (__nv_bfloat162*)g_hi;
            __nv_bfloat162* lo = (__nv_bfloat162*)g_lo;
            ho[gid * 2 + 0] = __nv_bfloat162(hx, hy);
            ho[gid * 2 + 1] = __nv_bfloat162(hz, hw);
            lo[gid * 2 + 0] = __nv_bfloat162(lx, ly);
            lo[gid * 2 + 1] = __nv_bfloat162(lz, lw);
        }
    }
    grid_sync(0);

    // ===== phase 1: triangular MMA — 32 warps, warp tile 16x8, split acc ===
    if (cta < 136) {
        int b = cta;
        int J = (int)((sqrtf(8.f * b + 1.f) - 1.f) * 0.5f);
        while ((J + 1) * (J + 2) / 2 <= b) J++;
        while (J * (J + 1) / 2 > b) J--;
        const int I = b - J * (J + 1) / 2;
        const int bm = I * 64, bn = J * 64;

        const int wm = (wid & 3) * 16;       // 4 warps in M
        const int wn = (wid >> 2) * 8;       // 8 warps in N

        float accA[4], accB[4];              // hi*hi | cross terms
#pragma unroll
        for (int q = 0; q < 4; q++) { accA[q] = 0.f; accB[q] = 0.f; }

        issue_chunk64(sb + 0 * STAGE_BYTES, tid, bm, bn, 0);
        issue_chunk64(sb + 1 * STAGE_BYTES, tid, bm, bn, 64);

        const int a_row = wm + (lane & 15);
        const int a_kb  = (lane >> 4) * 16;
        const int bl    = lane & 15;
        const int b_row = wn + (bl & 7);
        const int b_kb  = (bl >> 3) * 16;

        for (int it = 0; it < 8; it++) {
            if (it < 7) { CP_WAIT1(); } else { CP_WAIT0(); }
            __syncthreads();
            if (it + 2 < 8)
                issue_chunk64(sb + ((it + 2) % 3) * STAGE_BYTES, tid, bm, bn, (it + 2) * 64);

            const uint32_t aH = sb + (it % 3) * STAGE_BYTES;
            const uint32_t aL = aH + 8192, bH = aH + 16384, bL = aH + 24576;
#pragma unroll
            for (int kk = 0; kk < 4; kk++) {
                uint32_t ahi[4], alo[4], bhi[2], blo[2];
                {
                    uint32_t off = SW128((uint32_t)(a_row * 128 + kk * 32 + a_kb));
                    ldmatrix4(ahi, aH + off);
                    ldmatrix4(alo, aL + off);
                }
                {
                    uint32_t off = SW128((uint32_t)(b_row * 128 + kk * 32 + b_kb));
                    ldmatrix2(bhi, bH + off);
                    ldmatrix2(blo, bL + off);
                }
                mma16816(accA, ahi, bhi);    // hi*hi  (chain: 4 per chunk)
                mma16816(accB, ahi, blo);    // hi*lo  (chain: 8 per chunk)
                mma16816(accB, alo, bhi);    // lo*hi
            }
        }

        const int r0 = wm + (lane >> 2);
        const int c0 = wn + (lane & 3) * 2;
        float acc[4];
#pragma unroll
        for (int q = 0; q < 4; q++) acc[q] = accA[q] + accB[q];

        {
            float* p0 = g_sim + (size_t)(bm + r0) * N_SAMP + bn + c0;
            *(float2*)p0 = make_float2(acc[0], acc[1]);
            *(float2*)(p0 + 8 * N_SAMP) = make_float2(acc[2], acc[3]);
        }

        if (I != J) {
            float* st = (float*)smem;   // 64x65 padded transpose buffer
            __syncthreads();            // ring fully consumed; safe to overwrite
            st[r0 * 65 + c0]           = acc[0];
            st[r0 * 65 + c0 + 1]       = acc[1];
            st[(r0 + 8) * 65 + c0]     = acc[2];
            st[(r0 + 8) * 65 + c0 + 1] = acc[3];
            __syncthreads();
            {
                const int orow = tid >> 4;
                const int c = (tid & 15) * 4;
                float4 v = make_float4(st[(c + 0) * 65 + orow], st[(c + 1) * 65 + orow],
                                       st[(c + 2) * 65 + orow], st[(c + 3) * 65 + orow]);
                ((float4*)(g_sim + (size_t)(bn + orow) * N_SAMP + bm))[tid & 15] = v;
            }
        }
    }
    grid_sync(1);

    // ================= phase 2: loss — ONE fill, ONE sync, 112 tasks =======
    float* ep_base = (float*)smem;
    float* en_base = ep_base + 7 * N_SAMP;
    float warp_loss = 0.f;

#pragma unroll
    for (int u = tid; u < 1792; u += NTHR) {
        const int rg = u >> 8;                   // 0..6
        const int e4 = u & 255;
        const int i = cta + rg * NCTA;
        if (i < N_SAMP) {
            float4 v = ((const float4*)(g_sim + (size_t)i * N_SAMP))[e4];
            float4 epv = make_float4(
                exp_poly4(fmaf(-SCALE_P, v.x, SCALE_P * THRESH)),
                exp_poly4(fmaf(-SCALE_P, v.y, SCALE_P * THRESH)),
                exp_poly4(fmaf(-SCALE_P, v.z, SCALE_P * THRESH)),
                exp_poly4(fmaf(-SCALE_P, v.w, SCALE_P * THRESH)));
            float4 env = make_float4(
                exp_poly3(fmaf(SCALE_N, v.x, -SCALE_N * THRESH)),
                exp_poly3(fmaf(SCALE_N, v.y, -SCALE_N * THRESH)),
                exp_poly3(fmaf(SCALE_N, v.z, -SCALE_N * THRESH)),
                exp_poly3(fmaf(SCALE_N, v.w, -SCALE_N * THRESH)));
            ((float4*)(ep_base + rg * N_SAMP))[e4] = epv;
            ((float4*)(en_base + rg * N_SAMP))[e4] = env;
        }
    }
    __syncthreads();

    const float EP_EPS = exp_poly4(fmaf(-SCALE_P, ONE_EPS, SCALE_P * THRESH));
    const float KP     = exp_poly4(-SCALE_P * MARGIN);
    const float KN     = exp_poly3(-SCALE_N * MARGIN);

#pragma unroll
    for (int q = 0; q < 4; q++) {
        const int t = wid + q * 32;
        if (t >= 112) break;
        const int rg = t >> 4;
        const int c  = t & 15;
        const int i  = cta + rg * NCTA;
        if (i >= N_SAMP) continue;
        if (!((g_posmask[c][i >> 5] >> (i & 31)) & 1u)) continue;

        const float* ep_sh = ep_base + rg * N_SAMP;
        const float* en_sh = en_base + rg * N_SAMP;

        unsigned myword = g_posmask[c][lane];
        unsigned rotw = __funnelshift_r(myword, myword, lane);
        const int base = lane * 32;

        float en_minp = 1e30f, ep_minn = 1e30f;
#pragma unroll
        for (int b2 = 0; b2 < 32; b2++) {
            int j = base + ((b2 + lane) & 31);
            float ep = ep_sh[j];
            if ((rotw >> b2) & 1u) {
                if (ep > EP_EPS) en_minp = fminf(en_minp, en_sh[j]);
            } else {
                ep_minn = fminf(ep_minn, ep);
            }
        }
#pragma unroll
        for (int o = 16; o; o >>= 1) {
            en_minp = fminf(en_minp, __shfl_xor_sync(0xffffffffu, en_minp, o));
            ep_minn = fminf(ep_minn, __shfl_xor_sync(0xffffffffu, ep_minn, o));
        }
        float thr_p = fmaxf(ep_minn * KP, EP_EPS);
        float thr_n = (en_minp > 1e29f) ? 0.f : en_minp * KN;

        float ps = 0.f, ns = 0.f;
#pragma unroll
        for (int b2 = 0; b2 < 32; b2++) {
            int j = base + ((b2 + lane) & 31);
            if ((rotw >> b2) & 1u) {
                float ep = ep_sh[j];
                if (ep > thr_p) ps += ep;
            } else {
                float en = en_sh[j];
                if (en > thr_n) ns += en;
            }
        }
#pragma unroll
        for (int o = 16; o; o >>= 1) {
            ps += __shfl_xor_sync(0xffffffffu, ps, o);
            ns += __shfl_xor_sync(0xffffffffu, ns, o);
        }
        if (ps > 0.f && ns > 0.f && lane == 0)
            warp_loss += log1pf(ps) / SCALE_P + log1pf(ns) / SCALE_N;
    }

    if (lane == 0) warpres[wid] = warp_loss;
    __syncthreads();
    if (tid == 0) {
        float sum = 0.f;
#pragma unroll
        for (int q = 0; q < 32; q++) sum += warpres[q];
        g_partial[cta] = sum;
        __threadfence();
        unsigned t = atomicAdd(&bar_cnt[3], 1u);
        s_last = (t == NCTA - 1);
        if (s_last) bar_cnt[3] = 0;    // reset for graph replay
    }
    __syncthreads();

    // ================= phase 3: final reduction (last CTA) =================
    if (s_last) {
        __threadfence();
        float sum = (tid < NCTA) ? __ldcg(&g_partial[tid]) : 0.f;
        int anc = (tid < 512) ? __popc(__ldcg(&g_posmask[0][0] + tid)) : 0;
#pragma unroll
        for (int o = 16; o; o >>= 1) {
            sum += __shfl_xor_sync(0xffffffffu, sum, o);
            anc += __shfl_xor_sync(0xffffffffu, anc, o);
        }
        if (lane == 0) { redf[wid] = sum; redi[wid] = anc; }
        __syncthreads();
        if (tid == 0) {
            float tot = 0.f; int ta = 0;
#pragma unroll
            for (int q = 0; q < 32; q++) { tot += redf[q]; ta += redi[q]; }
            out[0] = (ta > 0) ? tot / (float)ta : 0.f;
        }
    }
}

// ============================================================
extern "C" void kernel_launch(void* const* d_in, const int* in_sizes, int n_in,
                              void* d_out, int out_size) {
    const float* feats = (const float*)d_in[0];   // (1024, 512) f32
    const int* labels  = (const int*)d_in[1];     // (1024, 16) i32
    float* out = (float*)d_out;

    static bool attr_set = false;
    if (!attr_set) {
        cudaFuncSetAttribute(fused_kernel, cudaFuncAttributeMaxDynamicSharedMemorySize,
                             SM_TOTAL);
        attr_set = true;
    }

    fused_kernel<<<NCTA, NTHR, SM_TOTAL>>>(feats, labels, out);
}

// round 17
// speedup vs baseline: 1.1039x; 1.1039x over previous
#include <cuda_runtime.h>
#include <cuda_bf16.h>
#include <math.h>
#include <cstdint>

#define N_SAMP 1024
#define N_FEAT 512
#define N_LAB  16

#define THRESH   0.5f
#define MARGIN   0.1f
#define SCALE_P  0.05f
#define SCALE_N  0.002f
#define ONE_EPS  0.99999f   // 1.0 - 1e-5

#define NCTA 148
#define NTHR 1024

// ---- scratch (no allocations allowed) ----
__device__ float          g_sim[N_SAMP * N_SAMP];        // 4 MB, L2-resident
__device__ unsigned       g_posmask[N_LAB][N_SAMP / 32];
__device__ float          g_partial[NCTA];
__device__ unsigned       bar_cnt[4];                    // zero-init, self-resetting
__device__ unsigned       bar_gen[4];                    // monotone across replays

// ============================================================
// PTX helpers (baseline ISA only)
// ============================================================
__device__ __forceinline__ uint32_t smem_u32(const void* p) {
    uint32_t a;
    asm("{ .reg .u64 t; cvta.to.shared.u64 t, %1; cvt.u32.u64 %0, t; }" : "=r"(a) : "l"(p));
    return a;
}
__device__ __forceinline__ void ldmatrix4(uint32_t* r, uint32_t addr) {
    asm volatile("ldmatrix.sync.aligned.m8n8.x4.shared.b16 {%0,%1,%2,%3}, [%4];"
        : "=r"(r[0]), "=r"(r[1]), "=r"(r[2]), "=r"(r[3]) : "r"(addr));
}
__device__ __forceinline__ void mma16816(float* d, const uint32_t* a, const uint32_t* b) {
    asm volatile("mma.sync.aligned.m16n8k16.row.col.f32.bf16.bf16.f32 "
        "{%0,%1,%2,%3}, {%4,%5,%6,%7}, {%8,%9}, {%0,%1,%2,%3};"
        : "+f"(d[0]), "+f"(d[1]), "+f"(d[2]), "+f"(d[3])
        : "r"(a[0]), "r"(a[1]), "r"(a[2]), "r"(a[3]), "r"(b[0]), "r"(b[1]));
}
#define STS128(addr, r0, r1, r2, r3) \
    asm volatile("st.shared.v4.b32 [%0], {%1,%2,%3,%4};" \
        :: "r"(addr), "r"(r0), "r"(r1), "r"(r2), "r"(r3) : "memory")
#define SW128(off) ((off) ^ (((off) >> 3) & 0x70))

// Taylor exp: strictly monotone, pure FMA.
__device__ __forceinline__ float exp_poly4(float x) {   // |x| <= 0.08
    float e = fmaf(x, 1.f / 24.f, 1.f / 6.f);
    e = fmaf(x, e, 0.5f);
    e = fmaf(x, e, 1.0f);
    e = fmaf(x, e, 1.0f);
    return e;
}
__device__ __forceinline__ float exp_poly3(float x) {   // |x| <= 0.004
    float e = fmaf(x, 1.f / 6.f, 0.5f);
    e = fmaf(x, e, 1.0f);
    e = fmaf(x, e, 1.0f);
    return e;
}

// Device-wide barrier: all NCTA CTAs resident (grid 148 <= SM count, occ >= 1).
__device__ __forceinline__ void grid_sync(int b) {
    __syncthreads();
    if (threadIdx.x == 0) {
        __threadfence();
        unsigned g;
        asm volatile("ld.acquire.gpu.u32 %0, [%1];" : "=r"(g) : "l"(&bar_gen[b]));
        unsigned t = atomicAdd(&bar_cnt[b], 1u);
        if (t == NCTA - 1) {
            bar_cnt[b] = 0;
            asm volatile("st.release.gpu.u32 [%0], %1;" :: "l"(&bar_gen[b]), "r"(g + 1u));
        } else {
            unsigned cur;
            do {
                asm volatile("ld.acquire.gpu.u32 %0, [%1];" : "=r"(cur) : "l"(&bar_gen[b]));
            } while (cur == g);
        }
    }
    __syncthreads();
}

// ============================================================
// Fused loader: LDG fp32 chunk -> split bf16 hi/lo -> STS (SW128).
// Per chunk: A tile 64x64 f32 (16KB) + B tile 64x64 f32 (16KB).
// Thread side = tid>>9 (0=A rows bm.., 1=B rows bn..); 8 floats each.
// ============================================================
#define STAGE_BYTES 32768            // 8KB x (Ahi, Alo, Bhi, Blo)
#define SM_TOTAL 65536               // 2-stage ring

__device__ __forceinline__ void split8(const uint4 q0, const uint4 q1,
                                       uint32_t* ph, uint32_t* pl) {
    float f[8] = { __uint_as_float(q0.x), __uint_as_float(q0.y),
                   __uint_as_float(q0.z), __uint_as_float(q0.w),
                   __uint_as_float(q1.x), __uint_as_float(q1.y),
                   __uint_as_float(q1.z), __uint_as_float(q1.w) };
#pragma unroll
    for (int j = 0; j < 4; j++) {
        __nv_bfloat16 h0 = __float2bfloat16(f[2 * j]);
        __nv_bfloat16 h1 = __float2bfloat16(f[2 * j + 1]);
        __nv_bfloat16 l0 = __float2bfloat16(f[2 * j]     - __bfloat162float(h0));
        __nv_bfloat16 l1 = __float2bfloat16(f[2 * j + 1] - __bfloat162float(h1));
        __nv_bfloat162 hh(h0, h1), ll(l0, l1);
        ph[j] = *(uint32_t*)&hh;
        pl[j] = *(uint32_t*)&ll;
    }
}

// ============================================================
// THE fused persistent kernel.  <<<148, 1024, 64KB>>>
// ============================================================
__global__ void __launch_bounds__(1024, 1) fused_kernel(const float* __restrict__ F,
                                                        const int* __restrict__ labels,
                                                        float* __restrict__ out) {
    extern __shared__ char smem[];
    const uint32_t sb = smem_u32(smem);
    const int cta  = blockIdx.x;
    const int tid  = threadIdx.x;
    const int wid  = tid >> 5;
    const int lane = tid & 31;

    __shared__ float warpres[32];
    __shared__ float redf[32];
    __shared__ int   redi[32];
    __shared__ int   s_last;

    // ================= phase 1: triangular MMA with fused fp32->bf16 split =
    if (cta < 136) {
        int b = cta;
        int J = (int)((sqrtf(8.f * b + 1.f) - 1.f) * 0.5f);
        while ((J + 1) * (J + 2) / 2 <= b) J++;
        while (J * (J + 1) / 2 > b) J--;
        const int I = b - J * (J + 1) / 2;
        const int bm = I * 64, bn = J * 64;

        // loader mapping: side 0 = A (rows bm..), side 1 = B (rows bn..)
        const int side   = tid >> 9;
        const int within = tid & 511;
        const int lrow   = within >> 3;          // 0..63
        const int lseg   = within & 7;           // 8 floats each
        const float* Fp  = F + (size_t)((side ? bn : bm) + lrow) * N_FEAT + lseg * 8;
        const uint32_t sts_off = SW128((uint32_t)(lrow * 128 + lseg * 16));
        const uint32_t sts_hi_base = sb + side * 16384 + sts_off;          // Ahi/Bhi
        const uint32_t sts_lo_base = sts_hi_base + 8192;                   // Alo/Blo

        const int wm = (wid & 3) * 16;
        const int wn = ((wid >> 2) & 3) * 16;

        float acc[2][4];
#pragma unroll
        for (int nt = 0; nt < 2; nt++)
#pragma unroll
            for (int q = 0; q < 4; q++) acc[nt][q] = 0.f;

        const int a_row = wm + (lane & 15);
        const int a_kb  = (lane >> 4) * 16;
        const int b_row = wn + ((lane >> 4) << 3) + (lane & 7);
        const int b_kb  = ((lane >> 3) & 1) << 4;

        // prefetch chunk 0
        uint4 q0 = *(const uint4*)(Fp);
        uint4 q1 = *(const uint4*)(Fp + 4);

        for (int it = 0; it < 8; it++) {
            // convert + store chunk it into stage it&1
            {
                uint32_t ph[4], pl[4];
                split8(q0, q1, ph, pl);
                const uint32_t stg = (uint32_t)(it & 1) * STAGE_BYTES;
                STS128(sts_hi_base + stg, ph[0], ph[1], ph[2], ph[3]);
                STS128(sts_lo_base + stg, pl[0], pl[1], pl[2], pl[3]);
            }
            // prefetch chunk it+1 (LDG issued before the sync)
            if (it + 1 < 8) {
                const float* nf = Fp + (it + 1) * 64;
                q0 = *(const uint4*)(nf);
                q1 = *(const uint4*)(nf + 4);
            }
            __syncthreads();

            if (wid < 16) {
                const uint32_t aH = sb + (uint32_t)(it & 1) * STAGE_BYTES;
                const uint32_t aL = aH + 8192, bH = aH + 16384, bL = aH + 24576;
#pragma unroll
                for (int kk = 0; kk < 4; kk++) {
                    uint32_t ahi[4], alo[4], bhi[4], blo[4];
                    {
                        uint32_t off = SW128((uint32_t)(a_row * 128 + kk * 32 + a_kb));
                        ldmatrix4(ahi, aH + off);
                        ldmatrix4(alo, aL + off);
                    }
                    {
                        uint32_t off = SW128((uint32_t)(b_row * 128 + kk * 32 + b_kb));
                        ldmatrix4(bhi, bH + off);
                        ldmatrix4(blo, bL + off);
                    }
#pragma unroll
                    for (int nt = 0; nt < 2; nt++) {
                        mma16816(acc[nt], ahi, &bhi[nt * 2]);   // hi*hi
                        mma16816(acc[nt], ahi, &blo[nt * 2]);   // hi*lo
                        mma16816(acc[nt], alo, &bhi[nt * 2]);   // lo*hi
                    }
                }
            }
        }

        const int r0 = wm + (lane >> 2);
        const int c0 = wn + (lane & 3) * 2;
        if (wid < 16) {
#pragma unroll
            for (int nt = 0; nt < 2; nt++) {
                float* p0 = g_sim + (size_t)(bm + r0) * N_SAMP + bn + c0 + nt * 8;
                *(float2*)p0 = make_float2(acc[nt][0], acc[nt][1]);
                *(float2*)(p0 + 8 * N_SAMP) = make_float2(acc[nt][2], acc[nt][3]);
            }
        }

        if (I != J) {
            float* st = (float*)smem;   // 64x65 padded transpose buffer
            __syncthreads();            // ring fully consumed; safe to overwrite
            if (wid < 16) {
#pragma unroll
                for (int nt = 0; nt < 2; nt++) {
                    int lc = c0 + nt * 8;
                    st[r0 * 65 + lc]           = acc[nt][0];
                    st[r0 * 65 + lc + 1]       = acc[nt][1];
                    st[(r0 + 8) * 65 + lc]     = acc[nt][2];
                    st[(r0 + 8) * 65 + lc + 1] = acc[nt][3];
                }
            }
            __syncthreads();
            {
                const int orow = tid >> 4;
                const int c = (tid & 15) * 4;
                float4 v = make_float4(st[(c + 0) * 65 + orow], st[(c + 1) * 65 + orow],
                                       st[(c + 2) * 65 + orow], st[(c + 3) * 65 + orow]);
                ((float4*)(g_sim + (size_t)(bn + orow) * N_SAMP + bm))[tid & 15] = v;
            }
        }
    } else if (cta == 147) {
        // labels -> posmask (visible to all after grid_sync(0))
        const int row = wid * 32 + lane;
        const int4* lp = (const int4*)(labels + row * N_LAB);
        int4 L0 = lp[0], L1 = lp[1], L2 = lp[2], L3 = lp[3];
        int lab[16] = { L0.x, L0.y, L0.z, L0.w, L1.x, L1.y, L1.z, L1.w,
                        L2.x, L2.y, L2.z, L2.w, L3.x, L3.y, L3.z, L3.w };
#pragma unroll
        for (int c = 0; c < 16; c++) {
            unsigned m = __ballot_sync(0xffffffffu, lab[c] == 1);
            if (lane == c) g_posmask[c][wid] = m;
        }
    }
    grid_sync(0);

    // ================= phase 2: loss — ONE fill, ONE sync, 112 tasks =======
    float* ep_base = (float*)smem;
    float* en_base = ep_base + 7 * N_SAMP;
    float warp_loss = 0.f;

#pragma unroll
    for (int u = tid; u < 1792; u += NTHR) {
        const int rg = u >> 8;                   // 0..6
        const int e4 = u & 255;
        const int i = cta + rg * NCTA;
        if (i < N_SAMP) {
            float4 v = ((const float4*)(g_sim + (size_t)i * N_SAMP))[e4];
            float4 epv = make_float4(
                exp_poly4(fmaf(-SCALE_P, v.x, SCALE_P * THRESH)),
                exp_poly4(fmaf(-SCALE_P, v.y, SCALE_P * THRESH)),
                exp_poly4(fmaf(-SCALE_P, v.z, SCALE_P * THRESH)),
                exp_poly4(fmaf(-SCALE_P, v.w, SCALE_P * THRESH)));
            float4 env = make_float4(
                exp_poly3(fmaf(SCALE_N, v.x, -SCALE_N * THRESH)),
                exp_poly3(fmaf(SCALE_N, v.y, -SCALE_N * THRESH)),
                exp_poly3(fmaf(SCALE_N, v.z, -SCALE_N * THRESH)),
                exp_poly3(fmaf(SCALE_N, v.w, -SCALE_N * THRESH)));
            ((float4*)(ep_base + rg * N_SAMP))[e4] = epv;
            ((float4*)(en_base + rg * N_SAMP))[e4] = env;
        }
    }
    __syncthreads();

    const float EP_EPS = exp_poly4(fmaf(-SCALE_P, ONE_EPS, SCALE_P * THRESH));
    const float KP     = exp_poly4(-SCALE_P * MARGIN);
    const float KN     = exp_poly3(-SCALE_N * MARGIN);

#pragma unroll
    for (int q = 0; q < 4; q++) {
        const int t = wid + q * 32;
        if (t >= 112) break;
        const int rg = t >> 4;
        const int c  = t & 15;
        const int i  = cta + rg * NCTA;
        if (i >= N_SAMP) continue;
        if (!((g_posmask[c][i >> 5] >> (i & 31)) & 1u)) continue;

        const float* ep_sh = ep_base + rg * N_SAMP;
        const float* en_sh = en_base + rg * N_SAMP;

        unsigned myword = g_posmask[c][lane];
        unsigned rotw = __funnelshift_r(myword, myword, lane);
        const int base = lane * 32;

        float en_minp = 1e30f, ep_minn = 1e30f;
#pragma unroll
        for (int b2 = 0; b2 < 32; b2++) {
            int j = base + ((b2 + lane) & 31);
            float ep = ep_sh[j];
            if ((rotw >> b2) & 1u) {
                if (ep > EP_EPS) en_minp = fminf(en_minp, en_sh[j]);
            } else {
                ep_minn = fminf(ep_minn, ep);
            }
        }
#pragma unroll
        for (int o = 16; o; o >>= 1) {
            en_minp = fminf(en_minp, __shfl_xor_sync(0xffffffffu, en_minp, o));
            ep_minn = fminf(ep_minn, __shfl_xor_sync(0xffffffffu, ep_minn, o));
        }
        float thr_p = fmaxf(ep_minn * KP, EP_EPS);
        float thr_n = (en_minp > 1e29f) ? 0.f : en_minp * KN;

        float ps = 0.f, ns = 0.f;
#pragma unroll
        for (int b2 = 0; b2 < 32; b2++) {
            int j = base + ((b2 + lane) & 31);
            if ((rotw >> b2) & 1u) {
                float ep = ep_sh[j];
                if (ep > thr_p) ps += ep;
            } else {
                float en = en_sh[j];
                if (en > thr_n) ns += en;
            }
        }
#pragma unroll
        for (int o = 16; o; o >>= 1) {
            ps += __shfl_xor_sync(0xffffffffu, ps, o);
            ns += __shfl_xor_sync(0xffffffffu, ns, o);
        }
        if (ps > 0.f && ns > 0.f && lane == 0)
            warp_loss += log1pf(ps) / SCALE_P + log1pf(ns) / SCALE_N;
    }

    if (lane == 0) warpres[wid] = warp_loss;
    __syncthreads();
    if (tid == 0) {
        float sum = 0.f;
#pragma unroll
        for (int q = 0; q < 32; q++) sum += warpres[q];
        g_partial[cta] = sum;
        __threadfence();
        unsigned t = atomicAdd(&bar_cnt[3], 1u);
        s_last = (t == NCTA - 1);
        if (s_last) bar_cnt[3] = 0;    // reset for graph replay
    }
    __syncthreads();

    // ================= phase 3: final reduction (last CTA) =================
    if (s_last) {
        __threadfence();
        float sum = (tid < NCTA) ? __ldcg(&g_partial[tid]) : 0.f;
        int anc = (tid < 512) ? __popc(__ldcg(&g_posmask[0][0] + tid)) : 0;
#pragma unroll
        for (int o = 16; o; o >>= 1) {
            sum += __shfl_xor_sync(0xffffffffu, sum, o);
            anc += __shfl_xor_sync(0xffffffffu, anc, o);
        }
        if (lane == 0) { redf[wid] = sum; redi[wid] = anc; }
        __syncthreads();
        if (tid == 0) {
            float tot = 0.f; int ta = 0;
#pragma unroll
            for (int q = 0; q < 32; q++) { tot += redf[q]; ta += redi[q]; }
            out[0] = (ta > 0) ? tot / (float)ta : 0.f;
        }
    }
}

// ============================================================
extern "C" void kernel_launch(void* const* d_in, const int* in_sizes, int n_in,
                              void* d_out, int out_size) {
    const float* feats = (const float*)d_in[0];   // (1024, 512) f32
    const int* labels  = (const int*)d_in[1];     // (1024, 16) i32
    float* out = (float*)d_out;

    static bool attr_set = false;
    if (!attr_set) {
        cudaFuncSetAttribute(fused_kernel, cudaFuncAttributeMaxDynamicSharedMemorySize,
                             SM_TOTAL);
        attr_set = true;
    }

    fused_kernel<<<NCTA, NTHR, SM_TOTAL>>>(feats, labels, out);
}